// round 1
// baseline (speedup 1.0000x reference)
#include <cuda_runtime.h>
#include <cuda_bf16.h>

// Problem constants (match reference_code)
#define B_DIM 4
#define L_DIM 4096
#define D_DIM 1024
#define NUM_KEEP 1024
#define NUM_DROP (L_DIM - NUM_KEEP)

// Output layout (flattened tuple, all float32):
//   [0)                      outputs_dropped : B * NUM_KEEP * D   = 4,194,304
//   [OFF_MASKED)             outputs_masked  : B * L * D          = 16,777,216
//   [OFF_MASKDROP)           mask_drop       : L                  = 4,096
//   [OFF_IDX)                idx_keep        : NUM_KEEP           = 1,024
#define OFF_MASKED   (B_DIM * NUM_KEEP * D_DIM)
#define OFF_MASKDROP (OFF_MASKED + B_DIM * L_DIM * D_DIM)
#define OFF_IDX      (OFF_MASKDROP + L_DIM)

// Device-global scratch (allocation-free): flag[l] = 0 if dropped, k+1 if kept
// with rank k (idx_keep is sorted, so rank in idx_keep == output row k).
__device__ int g_flag[L_DIM];

// ---------------------------------------------------------------------------
// Kernel 1: build flag map, emit mask_drop and idx_keep echo.
// Launch: <<<1, 1024>>>
// ---------------------------------------------------------------------------
__global__ void mask_prep_kernel(const int* __restrict__ idx_keep,
                                 float* __restrict__ out) {
    const int t = threadIdx.x;  // 0..1023

    // zero flags (4096 entries, 4 per thread)
    #pragma unroll
    for (int i = t; i < L_DIM; i += 1024) g_flag[i] = 0;
    __syncthreads();

    // scatter rank+1; also echo idx_keep into the float output
    const int idx = idx_keep[t];
    g_flag[idx] = t + 1;
    out[OFF_IDX + t] = (float)idx;
    __syncthreads();

    // mask_drop = (flag == 0) ? 1 : 0
    #pragma unroll
    for (int i = t; i < L_DIM; i += 1024) {
        out[OFF_MASKDROP + i] = (g_flag[i] == 0) ? 1.0f : 0.0f;
    }
}

// ---------------------------------------------------------------------------
// Kernel 2: fused gather + mask-fill. One block per (b,l) row, 256 threads,
// one float4 per thread (D=1024 floats = 256 float4).
// Launch: <<<B*L, 256>>>
// ---------------------------------------------------------------------------
__global__ void __launch_bounds__(256, 8)
mask_main_kernel(const float4* __restrict__ inputs,
                 const float4* __restrict__ mask_embedding,
                 float* __restrict__ out) {
    const int row = blockIdx.x;          // 0 .. B*L-1
    const int b   = row >> 12;           // row / L_DIM
    const int l   = row & (L_DIM - 1);   // row % L_DIM
    const int tid = threadIdx.x;         // 0..255

    float4* __restrict__ dropped = (float4*)(out);               // [B, NUM_KEEP, D]
    float4* __restrict__ masked  = (float4*)(out + OFF_MASKED);  // [B, L, D]

    const int flag = g_flag[l];
    const size_t row_f4 = (size_t)row * (D_DIM / 4);

    if (flag) {
        // keep row: pass input through to masked, and gather into dropped[k]
        const int k = flag - 1;
        float4 v = __ldg(&inputs[row_f4 + tid]);
        masked[row_f4 + tid] = v;
        dropped[((size_t)b * NUM_KEEP + k) * (D_DIM / 4) + tid] = v;
    } else {
        // drop row: broadcast mask_embedding (4 KB, L2-resident)
        masked[row_f4 + tid] = __ldg(&mask_embedding[tid]);
    }
}

// ---------------------------------------------------------------------------
extern "C" void kernel_launch(void* const* d_in, const int* in_sizes, int n_in,
                              void* d_out, int out_size) {
    const float4* inputs         = (const float4*)d_in[0];  // [B, L, D] f32
    const float4* mask_embedding = (const float4*)d_in[1];  // [D] f32
    const int*    idx_keep       = (const int*)d_in[2];     // [NUM_KEEP] i32
    float*        out            = (float*)d_out;

    mask_prep_kernel<<<1, 1024>>>(idx_keep, out);
    mask_main_kernel<<<B_DIM * L_DIM, 256>>>(inputs, mask_embedding, out);
}

// round 3
// speedup vs baseline: 1.1199x; 1.1199x over previous
#include <cuda_runtime.h>
#include <cuda_bf16.h>

// Problem constants (match reference_code)
#define B_DIM 4
#define L_DIM 4096
#define D_DIM 1024
#define NUM_KEEP 1024
#define NUM_DROP (L_DIM - NUM_KEEP)

// Output layout (flattened tuple, all float32):
//   [0)            outputs_dropped : B * NUM_KEEP * D   = 4,194,304
//   [OFF_MASKED)   outputs_masked  : B * L * D          = 16,777,216
//   [OFF_MASKDROP) mask_drop       : L                  = 4,096
//   [OFF_IDX)      idx_keep echo   : NUM_KEEP           = 1,024
#define OFF_MASKED   (B_DIM * NUM_KEEP * D_DIM)
#define OFF_MASKDROP (OFF_MASKED + B_DIM * L_DIM * D_DIM)
#define OFF_IDX      (OFF_MASKDROP + L_DIM)

#define ROWS_PER_BLOCK 8
#define MAIN_BLOCKS   ((B_DIM * L_DIM) / ROWS_PER_BLOCK)   // 2048
#define TAIL_BLOCKS   16                                    // mask_drop (+idx echo)
#define TOTAL_BLOCKS  (MAIN_BLOCKS + TAIL_BLOCKS)

// lower_bound over 1024 sorted ints in shared memory.
// Worst-case interval shrink is floor(n/2) per step: 1024 -> 1 after 10 steps,
// -> 0 after 11. MUST run 11 iterations to fully converge (R2 bug: ran 10).
__device__ __forceinline__ int lower_bound_1024(const int* __restrict__ s_idx, int v) {
    int lo = 0, hi = NUM_KEEP;
    #pragma unroll
    for (int it = 0; it < 11; ++it) {
        if (lo < hi) {
            int mid = (lo + hi) >> 1;
            if (s_idx[mid] < v) lo = mid + 1; else hi = mid;
        }
    }
    return lo;
}

__global__ void __launch_bounds__(256)
mask_fused_kernel(const float4* __restrict__ inputs,
                  const float4* __restrict__ mask_embedding,
                  const int4*  __restrict__ idx_keep,
                  float* __restrict__ out) {
    __shared__ int s_idx[NUM_KEEP];
    __shared__ int s_flag[ROWS_PER_BLOCK];

    const int tid = threadIdx.x;   // 0..255
    const int bid = blockIdx.x;

    // Load sorted idx_keep into shared (4 KB; one int4 per thread).
    {
        int4 q = __ldg(&idx_keep[tid]);
        ((int4*)s_idx)[tid] = q;
    }
    __syncthreads();

    if (bid < MAIN_BLOCKS) {
        // ----- main path: 8 consecutive (b,l) rows, one float4 column/thread
        const int row0 = bid * ROWS_PER_BLOCK;

        // 8 threads do the per-row membership searches
        if (tid < ROWS_PER_BLOCK) {
            const int l = (row0 + tid) & (L_DIM - 1);
            int pos = lower_bound_1024(s_idx, l);
            s_flag[tid] = (pos < NUM_KEEP && s_idx[pos] == l) ? (pos + 1) : 0;
        }
        __syncthreads();

        float4* __restrict__ dropped = (float4*)(out);               // [B,K,D]
        float4* __restrict__ masked  = (float4*)(out + OFF_MASKED);  // [B,L,D]
        const float4 me = __ldg(&mask_embedding[tid]);

        int flags[ROWS_PER_BLOCK];
        #pragma unroll
        for (int r = 0; r < ROWS_PER_BLOCK; ++r) flags[r] = s_flag[r];

        // front-batch the keep-row loads for MLP
        float4 v[ROWS_PER_BLOCK];
        #pragma unroll
        for (int r = 0; r < ROWS_PER_BLOCK; ++r) {
            if (flags[r]) {
                v[r] = __ldg(&inputs[(size_t)(row0 + r) * (D_DIM / 4) + tid]);
            }
        }

        #pragma unroll
        for (int r = 0; r < ROWS_PER_BLOCK; ++r) {
            const int    row    = row0 + r;
            const size_t row_f4 = (size_t)row * (D_DIM / 4);
            if (flags[r]) {
                const int b = row >> 12;           // row / L_DIM
                const int k = flags[r] - 1;
                masked[row_f4 + tid] = v[r];
                dropped[((size_t)b * NUM_KEEP + k) * (D_DIM / 4) + tid] = v[r];
            } else {
                masked[row_f4 + tid] = me;
            }
        }
    } else {
        // ----- tail path: mask_drop (4096 vals over 16 blocks) + idx echo
        const int tb = bid - MAIN_BLOCKS;          // 0..15
        const int i  = tb * 256 + tid;             // 0..4095
        int pos = lower_bound_1024(s_idx, i);
        bool kept = (pos < NUM_KEEP && s_idx[pos] == i);
        out[OFF_MASKDROP + i] = kept ? 0.0f : 1.0f;
        if (tb < 4) {
            const int j = tb * 256 + tid;          // 0..1023
            out[OFF_IDX + j] = (float)s_idx[j];
        }
    }
}

// ---------------------------------------------------------------------------
extern "C" void kernel_launch(void* const* d_in, const int* in_sizes, int n_in,
                              void* d_out, int out_size) {
    const float4* inputs         = (const float4*)d_in[0];  // [B, L, D] f32
    const float4* mask_embedding = (const float4*)d_in[1];  // [D] f32
    const int4*   idx_keep       = (const int4*)d_in[2];    // [NUM_KEEP] i32
    float*        out            = (float*)d_out;

    mask_fused_kernel<<<TOTAL_BLOCKS, 256>>>(inputs, mask_embedding, idx_keep, out);
}